// round 13
// baseline (speedup 1.0000x reference)
#include <cuda_runtime.h>
#include <cstdint>

#define BQ     32
#define NKEYS  4096
#define DIM    64
#define NQ     8
#define CPB    16         // chunks per batch -> grid 512
#define CHUNK  256        // keys per CTA (4 warps x 64)
#define WKEYS  64         // keys per warp: 2 tiles of 32, lane = key-in-tile
#define NT     2          // tiles per warp
#define KHROW  36         // floats per K half-row (32 + 4 pad) -> conflict-free
#define PROW   20         // floats per splatted-P row (16 + 4 pad) -> conflict-free
#define BUFSZ  1152       // floats per ring buffer (fits K half 32x36 or V half 16x64)

typedef unsigned long long u64;

// ---- global scratch ----
__device__ float    g_pv[BQ * CPB * NQ * DIM];
__device__ float    g_cs[BQ * CPB * NQ];
__device__ unsigned g_cnt[BQ];

// ---- cp.async ----
__device__ __forceinline__ void cp16(uint32_t s, const float* g) {
    asm volatile("cp.async.cg.shared.global [%0], [%1], 16;\n" :: "r"(s), "l"(g));
}
__device__ __forceinline__ void cp_commit() {
    asm volatile("cp.async.commit_group;\n" ::: "memory");
}
template <int N>
__device__ __forceinline__ void cp_wait() {
    asm volatile("cp.async.wait_group %0;\n" :: "n"(N) : "memory");
}

// ---- packed f32x2 ----
__device__ __forceinline__ void fma2(u64& d, u64 a, u64 b) {
    asm("fma.rn.f32x2 %0, %1, %2, %0;" : "+l"(d) : "l"(a), "l"(b));
}
__device__ __forceinline__ float f2lo(u64 x) { return __uint_as_float((unsigned)x); }
__device__ __forceinline__ float f2hi(u64 x) { return __uint_as_float((unsigned)(x >> 32)); }
__device__ __forceinline__ u64 splat2(float p) {
    u64 r; asm("mov.b64 %0, {%1, %1};" : "=l"(r) : "f"(p)); return r;
}

// ---- smem layout (float offsets) ----
// Q (prescaled): 8 x 64 = 512 floats at 0 (uniform reads)
// per-warp region: ring buf0|buf1|buf2 (1152 each) | P (32x20 = 640)
//   buf0 reused as the epilogue reduction area at the end.
#define W_P     (3 * BUFSZ)                    // 3456
#define W_SZ    (W_P + 640)                    // 4096
#define OFF_Q   0
#define OFF_W(w) (512 + (w) * W_SZ)
#define SMEM_FLOATS (512 + 4 * W_SZ)           // 16896 floats = 67,584 B -> 3 CTAs/SM

extern __shared__ float smem[];

__global__ __launch_bounds__(128, 3)
void attn_fused(const float* __restrict__ keys,
                const float* __restrict__ vals,
                const float* __restrict__ query,
                float* __restrict__ out) {
    const int tid  = threadIdx.x;
    const int lane = tid & 31;     // = this lane's key within the current tile
    const int warp = tid >> 5;
    const int b     = blockIdx.x >> 4;
    const int chunk = blockIdx.x & 15;
    const int n0    = chunk * CHUNK;
    __shared__ int s_last;

    const uint32_t sbase = (uint32_t)__cvta_generic_to_shared(smem);
    const uint32_t wbase = sbase + (uint32_t)(OFF_W(warp) << 2);

    const float* kgp = keys + ((size_t)b * NKEYS + n0 + warp * WKEYS) * DIM;
    const float* vgp = vals + ((size_t)b * NKEYS + n0 + warp * WKEYS) * DIM;

    // ---- stage K half h of tile t (dims 32h..+31, 32 keys) into ring buffer bf ----
    auto stage_k = [&](int t, int h, int bf) {
        const uint32_t kd = wbase + (uint32_t)((bf * BUFSZ) << 2);
        const float* kt = kgp + t * 32 * DIM;
#pragma unroll
        for (int i = 0; i < 8; ++i) {
            int c = i * 32 + lane;               // 0..255
            int k = c >> 3, i2 = c & 7;
            cp16(kd + (uint32_t)((k * KHROW + i2 * 4) << 2),
                 kt + k * DIM + h * 32 + i2 * 4);
        }
        cp_commit();
    };
    // ---- stage V half h of tile t (keys 16h..+15, full rows) into ring buffer bf ----
    auto stage_v = [&](int t, int h, int bf) {
        const uint32_t vd = wbase + (uint32_t)((bf * BUFSZ) << 2);
        const float* vt = vgp + (t * 32 + h * 16) * DIM;
#pragma unroll
        for (int i = 0; i < 8; ++i) {
            int c = i * 32 + lane;               // 0..255
            int k = c >> 4, i2 = c & 15;
            cp16(vd + (uint32_t)((k * DIM + i2 * 4) << 2),
                 vt + k * DIM + i2 * 4);
        }
        cp_commit();
    };

    // prologue: 3 groups in flight (K halves of tile 0 AND V half 0)
    stage_k(0, 0, 0);
    stage_k(0, 1, 1);
    stage_v(0, 0, 2);

    // ---- Q into smem, prescaled by 1/8 (uniform-read layout) ----
    {
        int r = tid >> 4, s = (tid & 15) << 2;
        float4 qv = *(const float4*)(query + ((size_t)b * NQ + r) * DIM + s);
        qv.x *= 0.125f; qv.y *= 0.125f; qv.z *= 0.125f; qv.w *= 0.125f;
        *(float4*)&smem[OFF_Q + r * DIM + s] = qv;
    }
    __syncthreads();

    const float* Wb = &smem[OFF_W(warp)];
    const float* Pbase = Wb + W_P;

    float cs[8];
#pragma unroll
    for (int m = 0; m < 8; ++m) cs[m] = 0.f;
    u64 pv[8];
#pragma unroll
    for (int m = 0; m < 8; ++m) pv[m] = 0ull;

#pragma unroll
    for (int t = 0; t < NT; ++t) {
        const int b0 = (4 * t) % 3, b1 = (4 * t + 1) % 3;
        const int b2 = (4 * t + 2) % 3, b3 = (4 * t + 3) % 3;

        u64 acc[8];
#pragma unroll
        for (int m = 0; m < 8; ++m) acc[m] = 0ull;

        // ===== phase 0: QK dims 0..31 (buffer b0), then refill b0 with V1(t) =====
        cp_wait<2>();  __syncwarp();
        {
            const float* Kr = Wb + b0 * BUFSZ + lane * KHROW;
#pragma unroll
            for (int i = 0; i < 8; ++i) {
                ulonglong2 kc = *(const ulonglong2*)(Kr + i * 4);
#pragma unroll
                for (int m = 0; m < 8; ++m) {
                    ulonglong2 qc = *(const ulonglong2*)&smem[OFF_Q + m * DIM + i * 4];
                    fma2(acc[m], kc.x, qc.x);
                    fma2(acc[m], kc.y, qc.y);
                }
            }
        }
        __syncwarp();
        stage_v(t, 1, b0);

        // ===== phase 1: QK dims 32..63 (buffer b1), then refill b1 with KA(t+1) =====
        cp_wait<2>();  __syncwarp();
        {
            const float* Kr = Wb + b1 * BUFSZ + lane * KHROW;
#pragma unroll
            for (int i = 0; i < 8; ++i) {
                ulonglong2 kc = *(const ulonglong2*)(Kr + i * 4);
#pragma unroll
                for (int m = 0; m < 8; ++m) {
                    ulonglong2 qc = *(const ulonglong2*)&smem[OFF_Q + m * DIM + 32 + i * 4];
                    fma2(acc[m], kc.x, qc.x);
                    fma2(acc[m], kc.y, qc.y);
                }
            }
        }
        __syncwarp();
        if (t + 1 < NT) stage_k(t + 1, 0, b1);

        // ===== softmax: lane-local, no shuffles =====
        {
            float e0 = __expf(f2lo(acc[0]) + f2hi(acc[0]));
            float e1 = __expf(f2lo(acc[1]) + f2hi(acc[1]));
            float e2 = __expf(f2lo(acc[2]) + f2hi(acc[2]));
            float e3 = __expf(f2lo(acc[3]) + f2hi(acc[3]));
            float e4 = __expf(f2lo(acc[4]) + f2hi(acc[4]));
            float e5 = __expf(f2lo(acc[5]) + f2hi(acc[5]));
            float e6 = __expf(f2lo(acc[6]) + f2hi(acc[6]));
            float e7 = __expf(f2lo(acc[7]) + f2hi(acc[7]));
            float sum = ((e0 + e1) + (e2 + e3)) + ((e4 + e5) + (e6 + e7));
            float inv = __fdividef(1.0f, sum);
            float p0 = fmaf(e0, inv, 1e-8f), p1 = fmaf(e1, inv, 1e-8f);
            float p2 = fmaf(e2, inv, 1e-8f), p3 = fmaf(e3, inv, 1e-8f);
            float p4 = fmaf(e4, inv, 1e-8f), p5 = fmaf(e5, inv, 1e-8f);
            float p6 = fmaf(e6, inv, 1e-8f), p7 = fmaf(e7, inv, 1e-8f);
            cs[0] += p0; cs[1] += p1; cs[2] += p2; cs[3] += p3;
            cs[4] += p4; cs[5] += p5; cs[6] += p6; cs[7] += p7;
            ulonglong2* Pq = (ulonglong2*)(Pbase + lane * PROW);
            Pq[0] = make_ulonglong2(splat2(p0), splat2(p1));
            Pq[1] = make_ulonglong2(splat2(p2), splat2(p3));
            Pq[2] = make_ulonglong2(splat2(p4), splat2(p5));
            Pq[3] = make_ulonglong2(splat2(p6), splat2(p7));
        }
        __syncwarp();                          // P visible to all lanes

        // ===== phase 2: PV keys 0..15 (buffer b2), then refill b2 with KB(t+1) =====
        if (t + 1 < NT) { cp_wait<2>(); } else { cp_wait<1>(); }
        __syncwarp();
        {
            const float* Vr = Wb + b2 * BUFSZ;
#pragma unroll
            for (int k = 0; k < 16; ++k) {
                const ulonglong2* Pq = (const ulonglong2*)(Pbase + k * PROW);
                ulonglong2 p01 = Pq[0], p23 = Pq[1], p45 = Pq[2], p67 = Pq[3];
                u64 v = *(const u64*)(Vr + k * DIM + (lane << 1));
                fma2(pv[0], p01.x, v); fma2(pv[1], p01.y, v);
                fma2(pv[2], p23.x, v); fma2(pv[3], p23.y, v);
                fma2(pv[4], p45.x, v); fma2(pv[5], p45.y, v);
                fma2(pv[6], p67.x, v); fma2(pv[7], p67.y, v);
            }
        }
        __syncwarp();
        if (t + 1 < NT) stage_k(t + 1, 1, b2);

        // ===== phase 3: PV keys 16..31 (buffer b3), then refill b3 with V0(t+1) =====
        if (t + 1 < NT) { cp_wait<2>(); } else { cp_wait<0>(); }
        __syncwarp();
        {
            const float* Vr = Wb + b3 * BUFSZ;
#pragma unroll
            for (int k = 0; k < 16; ++k) {
                const ulonglong2* Pq = (const ulonglong2*)(Pbase + (k + 16) * PROW);
                ulonglong2 p01 = Pq[0], p23 = Pq[1], p45 = Pq[2], p67 = Pq[3];
                u64 v = *(const u64*)(Vr + k * DIM + (lane << 1));
                fma2(pv[0], p01.x, v); fma2(pv[1], p01.y, v);
                fma2(pv[2], p23.x, v); fma2(pv[3], p23.y, v);
                fma2(pv[4], p45.x, v); fma2(pv[5], p45.y, v);
                fma2(pv[6], p67.x, v); fma2(pv[7], p67.y, v);
            }
        }
        __syncwarp();
        if (t + 1 < NT) stage_v(t + 1, 0, b3);
    }

    // ================= per-warp epilogue =================
    {
#pragma unroll
        for (int off = 16; off >= 1; off >>= 1) {
#pragma unroll
            for (int m = 0; m < 8; ++m)
                cs[m] += __shfl_xor_sync(0xffffffffu, cs[m], off);
        }
        float* red = &smem[OFF_W(warp)];       // reuses ring buffer 0
#pragma unroll
        for (int m = 0; m < 8; ++m)
            *(u64*)&red[m * 64 + (lane << 1)] = pv[m];
        if (lane == 0) {
#pragma unroll
            for (int m = 0; m < 8; ++m) red[512 + m] = cs[m];
        }
    }
    __syncthreads();

    const int pidx = (b * CPB + chunk) * NQ;
    if (tid < 8) {
        float s = 0.f;
#pragma unroll
        for (int w = 0; w < 4; ++w) s += smem[OFF_W(w) + 512 + tid];
        g_cs[pidx + tid] = s;
    }
    {
        int off = tid * 4;                    // 128 threads x float4 = 512 floats
        float4 s = make_float4(0.f, 0.f, 0.f, 0.f);
#pragma unroll
        for (int w = 0; w < 4; ++w) {
            float4 p = *(const float4*)&smem[OFF_W(w) + off];
            s.x += p.x; s.y += p.y; s.z += p.z; s.w += p.w;
        }
        *(float4*)&g_pv[(size_t)pidx * DIM + off] = s;
    }

    // ---- fused finalize: last chunk CTA of this batch ----
    __syncthreads();
    if (tid == 0) {
        __threadfence();
        unsigned old = atomicAdd(&g_cnt[b], 1u);
        s_last = (old == CPB - 1) ? 1 : 0;
    }
    __syncthreads();
    if (s_last) {
        __threadfence();
        int qm = tid >> 4, v4 = (tid & 15) << 2;
        float c0 = 0.f;
        float4 acc4 = make_float4(0.f, 0.f, 0.f, 0.f);
#pragma unroll
        for (int c = 0; c < CPB; ++c) {
            c0 += g_cs[(b * CPB + c) * NQ + qm];
            float4 p = *(const float4*)&g_pv[((size_t)(b * CPB + c) * NQ + qm) * DIM + v4];
            acc4.x += p.x; acc4.y += p.y; acc4.z += p.z; acc4.w += p.w;
        }
        float inv = 1.0f / c0;
        *(float4*)&out[((size_t)b * NQ + qm) * DIM + v4] =
            make_float4(acc4.x * inv, acc4.y * inv, acc4.z * inv, acc4.w * inv);
        if (tid == 0) g_cnt[b] = 0;   // reset for next graph replay
    }
}

extern "C" void kernel_launch(void* const* d_in, const int* in_sizes, int n_in,
                              void* d_out, int out_size) {
    const float* keys  = (const float*)d_in[0];
    const float* vals  = (const float*)d_in[1];
    const float* query = (const float*)d_in[2];
    float* out = (float*)d_out;

    cudaFuncSetAttribute(attn_fused,
                         cudaFuncAttributeMaxDynamicSharedMemorySize,
                         SMEM_FLOATS * sizeof(float));
    attn_fused<<<BQ * CPB, 128, SMEM_FLOATS * sizeof(float)>>>(keys, vals, query, out);
}

// round 14
// speedup vs baseline: 1.0784x; 1.0784x over previous
#include <cuda_runtime.h>
#include <cstdint>

#define BQ     32
#define NKEYS  4096
#define DIM    64
#define NQ     8
#define CPB    16         // chunks per batch -> grid 512 (one wave at 4 CTA/SM)
#define CHUNK  256        // keys per CTA (4 warps x 64)
#define WKEYS  64         // keys per warp: 2 tiles of 32, lane = key-in-tile
#define NT     2          // tiles per warp
#define KQROW  20         // floats per K quarter-row (16 + 4 pad) -> conflict-free
#define PROW   20         // floats per splatted-P row (16 + 4 pad) -> conflict-free
#define BUFSZ  640        // ring slot: K quarter (32x20) or V eighth (8x64=512)

typedef unsigned long long u64;

// ---- global scratch ----
__device__ float    g_pv[BQ * CPB * NQ * DIM];
__device__ float    g_cs[BQ * CPB * NQ];
__device__ unsigned g_cnt[BQ];

// ---- cp.async ----
__device__ __forceinline__ void cp16(uint32_t s, const float* g) {
    asm volatile("cp.async.cg.shared.global [%0], [%1], 16;\n" :: "r"(s), "l"(g));
}
__device__ __forceinline__ void cp_commit() {
    asm volatile("cp.async.commit_group;\n" ::: "memory");
}
template <int N>
__device__ __forceinline__ void cp_wait() {
    asm volatile("cp.async.wait_group %0;\n" :: "n"(N) : "memory");
}

// ---- packed f32x2 ----
__device__ __forceinline__ void fma2(u64& d, u64 a, u64 b) {
    asm("fma.rn.f32x2 %0, %1, %2, %0;" : "+l"(d) : "l"(a), "l"(b));
}
__device__ __forceinline__ float f2lo(u64 x) { return __uint_as_float((unsigned)x); }
__device__ __forceinline__ float f2hi(u64 x) { return __uint_as_float((unsigned)(x >> 32)); }
__device__ __forceinline__ u64 splat2(float p) {
    u64 r; asm("mov.b64 %0, {%1, %1};" : "=l"(r) : "f"(p)); return r;
}

// ---- smem layout (float offsets) ----
// Q (prescaled): 8 x 64 = 512 floats at 0 (uniform reads)
// per-warp region: ring slot0..3 (640 each) | P (32x20 = 640)
//   slot area reused as the epilogue reduction region at the end.
#define W_P     (4 * BUFSZ)                    // 2560
#define W_SZ    (W_P + 640)                    // 3200
#define OFF_Q   0
#define OFF_W(w) (512 + (w) * W_SZ)
#define SMEM_FLOATS (512 + 4 * W_SZ)           // 13312 floats = 53,248 B -> 4 CTAs/SM

extern __shared__ float smem[];

__global__ __launch_bounds__(128, 4)
void attn_fused(const float* __restrict__ keys,
                const float* __restrict__ vals,
                const float* __restrict__ query,
                float* __restrict__ out) {
    const int tid  = threadIdx.x;
    const int lane = tid & 31;     // = this lane's key within the current tile
    const int warp = tid >> 5;
    const int b     = blockIdx.x >> 4;
    const int chunk = blockIdx.x & 15;
    const int n0    = chunk * CHUNK;
    __shared__ int s_last;

    const uint32_t sbase = (uint32_t)__cvta_generic_to_shared(smem);
    const uint32_t wbase = sbase + (uint32_t)(OFF_W(warp) << 2);

    const float* kgp = keys + ((size_t)b * NKEYS + n0 + warp * WKEYS) * DIM;
    const float* vgp = vals + ((size_t)b * NKEYS + n0 + warp * WKEYS) * DIM;

    // ---- stage K quarter q of tile t (dims 16q..+15, 32 keys) into slot bf ----
    auto stage_kq = [&](int t, int q, int bf) {
        const uint32_t kd = wbase + (uint32_t)((bf * BUFSZ) << 2);
        const float* kt = kgp + t * 32 * DIM + q * 16;
#pragma unroll
        for (int i = 0; i < 4; ++i) {
            int c = i * 32 + lane;               // 0..127
            int k = c >> 2, i2 = c & 3;
            cp16(kd + (uint32_t)((k * KQROW + i2 * 4) << 2),
                 kt + k * DIM + i2 * 4);
        }
        cp_commit();
    };
    // ---- stage V eighth e of tile t (keys 8e..8e+7, full rows) into slot bf ----
    auto stage_ve = [&](int t, int e, int bf) {
        const uint32_t vd = wbase + (uint32_t)((bf * BUFSZ) << 2);
        const float* vt = vgp + (t * 32 + e * 8) * DIM;
#pragma unroll
        for (int i = 0; i < 4; ++i) {
            int c = i * 32 + lane;               // 0..127
            int k = c >> 4, i2 = c & 15;
            cp16(vd + (uint32_t)((k * DIM + i2 * 4) << 2),
                 vt + k * DIM + i2 * 4);
        }
        cp_commit();
    };

    // prologue: 4 groups in flight (K quarters of tile 0 -> slots 0..3)
    stage_kq(0, 0, 0); stage_kq(0, 1, 1); stage_kq(0, 2, 2); stage_kq(0, 3, 3);

    // ---- Q into smem, prescaled by 1/8 (uniform-read layout) ----
    {
        int r = tid >> 4, s = (tid & 15) << 2;
        float4 qv = *(const float4*)(query + ((size_t)b * NQ + r) * DIM + s);
        qv.x *= 0.125f; qv.y *= 0.125f; qv.z *= 0.125f; qv.w *= 0.125f;
        *(float4*)&smem[OFF_Q + r * DIM + s] = qv;
    }
    __syncthreads();

    const float* Wb = &smem[OFF_W(warp)];
    const float* Pbase = Wb + W_P;

    float cs[8];
#pragma unroll
    for (int m = 0; m < 8; ++m) cs[m] = 0.f;
    u64 pv[8];
#pragma unroll
    for (int m = 0; m < 8; ++m) pv[m] = 0ull;

#pragma unroll
    for (int t = 0; t < NT; ++t) {
        u64 acc[8];
#pragma unroll
        for (int m = 0; m < 8; ++m) acc[m] = 0ull;

        // ===== QK quarters: consume K slot q, refill with V eighth q =====
#pragma unroll
        for (int q = 0; q < 4; ++q) {
            cp_wait<3>();  __syncwarp();
            const float* Kr = Wb + q * BUFSZ + lane * KQROW;
#pragma unroll
            for (int i = 0; i < 4; ++i) {        // dims 16q+4i .. +3
                ulonglong2 kc = *(const ulonglong2*)(Kr + i * 4);
#pragma unroll
                for (int m = 0; m < 8; ++m) {
                    ulonglong2 qc = *(const ulonglong2*)&smem[OFF_Q + m * DIM + q * 16 + i * 4];
                    fma2(acc[m], kc.x, qc.x);
                    fma2(acc[m], kc.y, qc.y);
                }
            }
            __syncwarp();
            stage_ve(t, q, q);                   // slot q -> V keys 8q..8q+7
        }

        // ===== softmax: lane-local, no shuffles =====
        {
            float e0 = __expf(f2lo(acc[0]) + f2hi(acc[0]));
            float e1 = __expf(f2lo(acc[1]) + f2hi(acc[1]));
            float e2 = __expf(f2lo(acc[2]) + f2hi(acc[2]));
            float e3 = __expf(f2lo(acc[3]) + f2hi(acc[3]));
            float e4 = __expf(f2lo(acc[4]) + f2hi(acc[4]));
            float e5 = __expf(f2lo(acc[5]) + f2hi(acc[5]));
            float e6 = __expf(f2lo(acc[6]) + f2hi(acc[6]));
            float e7 = __expf(f2lo(acc[7]) + f2hi(acc[7]));
            float sum = ((e0 + e1) + (e2 + e3)) + ((e4 + e5) + (e6 + e7));
            float inv = __fdividef(1.0f, sum);
            float p0 = fmaf(e0, inv, 1e-8f), p1 = fmaf(e1, inv, 1e-8f);
            float p2 = fmaf(e2, inv, 1e-8f), p3 = fmaf(e3, inv, 1e-8f);
            float p4 = fmaf(e4, inv, 1e-8f), p5 = fmaf(e5, inv, 1e-8f);
            float p6 = fmaf(e6, inv, 1e-8f), p7 = fmaf(e7, inv, 1e-8f);
            cs[0] += p0; cs[1] += p1; cs[2] += p2; cs[3] += p3;
            cs[4] += p4; cs[5] += p5; cs[6] += p6; cs[7] += p7;
            ulonglong2* Pq = (ulonglong2*)(Pbase + lane * PROW);
            Pq[0] = make_ulonglong2(splat2(p0), splat2(p1));
            Pq[1] = make_ulonglong2(splat2(p2), splat2(p3));
            Pq[2] = make_ulonglong2(splat2(p4), splat2(p5));
            Pq[3] = make_ulonglong2(splat2(p6), splat2(p7));
        }
        __syncwarp();                          // P visible to all lanes

        // ===== PV eighths: consume V slot e, refill with K quarter e of t+1 =====
#pragma unroll
        for (int e = 0; e < 4; ++e) {
            if (t + 1 < NT) {
                cp_wait<3>();
            } else {
                if (e == 0)      cp_wait<3>();
                else if (e == 1) cp_wait<2>();
                else if (e == 2) cp_wait<1>();
                else             cp_wait<0>();
            }
            __syncwarp();
            const float* Vr = Wb + e * BUFSZ;
#pragma unroll
            for (int k = 0; k < 8; ++k) {
                const ulonglong2* Pq = (const ulonglong2*)(Pbase + (e * 8 + k) * PROW);
                ulonglong2 p01 = Pq[0], p23 = Pq[1], p45 = Pq[2], p67 = Pq[3];
                u64 v = *(const u64*)(Vr + k * DIM + (lane << 1));
                fma2(pv[0], p01.x, v); fma2(pv[1], p01.y, v);
                fma2(pv[2], p23.x, v); fma2(pv[3], p23.y, v);
                fma2(pv[4], p45.x, v); fma2(pv[5], p45.y, v);
                fma2(pv[6], p67.x, v); fma2(pv[7], p67.y, v);
            }
            __syncwarp();
            if (t + 1 < NT) stage_kq(t + 1, e, e);   // slot e -> next tile's K quarter e
        }
    }

    // ================= per-warp epilogue =================
    {
#pragma unroll
        for (int off = 16; off >= 1; off >>= 1) {
#pragma unroll
            for (int m = 0; m < 8; ++m)
                cs[m] += __shfl_xor_sync(0xffffffffu, cs[m], off);
        }
        float* red = &smem[OFF_W(warp)];       // reuses ring slots
#pragma unroll
        for (int m = 0; m < 8; ++m)
            *(u64*)&red[m * 64 + (lane << 1)] = pv[m];
        if (lane == 0) {
#pragma unroll
            for (int m = 0; m < 8; ++m) red[512 + m] = cs[m];
        }
    }
    __syncthreads();

    const int pidx = (b * CPB + chunk) * NQ;
    if (tid < 8) {
        float s = 0.f;
#pragma unroll
        for (int w = 0; w < 4; ++w) s += smem[OFF_W(w) + 512 + tid];
        g_cs[pidx + tid] = s;
    }
    {
        int off = tid * 4;                    // 128 threads x float4 = 512 floats
        float4 s = make_float4(0.f, 0.f, 0.f, 0.f);
#pragma unroll
        for (int w = 0; w < 4; ++w) {
            float4 p = *(const float4*)&smem[OFF_W(w) + off];
            s.x += p.x; s.y += p.y; s.z += p.z; s.w += p.w;
        }
        *(float4*)&g_pv[(size_t)pidx * DIM + off] = s;
    }

    // ---- fused finalize: last chunk CTA of this batch ----
    __syncthreads();
    if (tid == 0) {
        __threadfence();
        unsigned old = atomicAdd(&g_cnt[b], 1u);
        s_last = (old == CPB - 1) ? 1 : 0;
    }
    __syncthreads();
    if (s_last) {
        __threadfence();
        int qm = tid >> 4, v4 = (tid & 15) << 2;
        float c0 = 0.f;
        float4 acc4 = make_float4(0.f, 0.f, 0.f, 0.f);
#pragma unroll
        for (int c = 0; c < CPB; ++c) {
            c0 += g_cs[(b * CPB + c) * NQ + qm];
            float4 p = *(const float4*)&g_pv[((size_t)(b * CPB + c) * NQ + qm) * DIM + v4];
            acc4.x += p.x; acc4.y += p.y; acc4.z += p.z; acc4.w += p.w;
        }
        float inv = 1.0f / c0;
        *(float4*)&out[((size_t)b * NQ + qm) * DIM + v4] =
            make_float4(acc4.x * inv, acc4.y * inv, acc4.z * inv, acc4.w * inv);
        if (tid == 0) g_cnt[b] = 0;   // reset for next graph replay
    }
}

extern "C" void kernel_launch(void* const* d_in, const int* in_sizes, int n_in,
                              void* d_out, int out_size) {
    const float* keys  = (const float*)d_in[0];
    const float* vals  = (const float*)d_in[1];
    const float* query = (const float*)d_in[2];
    float* out = (float*)d_out;

    cudaFuncSetAttribute(attn_fused,
                         cudaFuncAttributeMaxDynamicSharedMemorySize,
                         SMEM_FLOATS * sizeof(float));
    attn_fused<<<BQ * CPB, 128, SMEM_FLOATS * sizeof(float)>>>(keys, vals, query, out);
}

// round 15
// speedup vs baseline: 1.1843x; 1.0982x over previous
#include <cuda_runtime.h>
#include <cstdint>

#define BQ     32
#define NKEYS  4096
#define DIM    64
#define NQ     8
#define CPB    16         // chunks per batch -> grid 512
#define CHUNK  256        // keys per CTA (4 warps x 64)
#define WKEYS  64         // keys per warp: 2 tiles of 32
#define NT     2
#define KHROW  36         // K half-row stride (32 dims + 4 pad); 36%8==4 -> kq reads conflict-free
#define PROW   10         // P row stride (8 + 2 pad)
#define QROW   68         // Q row stride (64 + 4 pad) -> distinct banks across mq
#define BUFSZ  1152       // ring buffer: K half (32x36) or V half (16x64)

typedef unsigned long long u64;

// ---- global scratch ----
__device__ float    g_pv[BQ * CPB * NQ * DIM];
__device__ float    g_cs[BQ * CPB * NQ];
__device__ unsigned g_cnt[BQ];

// ---- cp.async ----
__device__ __forceinline__ void cp16(uint32_t s, const float* g) {
    asm volatile("cp.async.cg.shared.global [%0], [%1], 16;\n" :: "r"(s), "l"(g));
}
__device__ __forceinline__ void cp_commit() {
    asm volatile("cp.async.commit_group;\n" ::: "memory");
}
template <int N>
__device__ __forceinline__ void cp_wait() {
    asm volatile("cp.async.wait_group %0;\n" :: "n"(N) : "memory");
}

// ---- packed f32x2 ----
__device__ __forceinline__ void fma2(u64& d, u64 a, u64 b) {
    asm("fma.rn.f32x2 %0, %1, %2, %0;" : "+l"(d) : "l"(a), "l"(b));
}
__device__ __forceinline__ float f2lo(u64 x) { return __uint_as_float((unsigned)x); }
__device__ __forceinline__ float f2hi(u64 x) { return __uint_as_float((unsigned)(x >> 32)); }
__device__ __forceinline__ u64 splat2(float p) {
    u64 r; asm("mov.b64 %0, {%1, %1};" : "=l"(r) : "f"(p)); return r;
}

// ---- smem layout (float offsets) ----
// Q (prescaled): 8 x QROW = 544 at 0
// per-warp: buf0 (1152) | buf1 (1152) | P (32x10 = 320)
//   buf0/1 hold K halves then V halves then next tile's K; buf0 reused as epilogue red.
#define W_P     (2 * BUFSZ)                    // 2304
#define W_SZ    (W_P + 320)                    // 2624
#define OFF_Q   0
#define OFF_W(w) (NQ * QROW + (w) * W_SZ)      // 544 + ...
#define SMEM_FLOATS (NQ * QROW + 4 * W_SZ)     // 11040 floats = 44,160 B -> 5 CTAs/SM

extern __shared__ float smem[];

__global__ __launch_bounds__(128, 5)
void attn_fused(const float* __restrict__ keys,
                const float* __restrict__ vals,
                const float* __restrict__ query,
                float* __restrict__ out) {
    const int tid  = threadIdx.x;
    const int lane = tid & 31;
    const int warp = tid >> 5;
    const int kq   = lane >> 2;        // QK: key group (keys kq+8r)
    const int mq   = lane & 3;         // QK: query pair (2mq, 2mq+1)
    const int mq2  = lane >> 3;        // PV: query pair (2mq2, 2mq2+1)
    const int vq   = lane & 7;         // PV: v chunks {4vq..+3, 32+4vq..+3}
    const int b     = blockIdx.x >> 4;
    const int chunk = blockIdx.x & 15;
    const int n0    = chunk * CHUNK;
    __shared__ int s_last;

    const uint32_t sbase = (uint32_t)__cvta_generic_to_shared(smem);
    const uint32_t wbase = sbase + (uint32_t)(OFF_W(warp) << 2);

    const float* kgp = keys + ((size_t)b * NKEYS + n0 + warp * WKEYS) * DIM;
    const float* vgp = vals + ((size_t)b * NKEYS + n0 + warp * WKEYS) * DIM;

    // ---- stage K half h of tile t (dims 32h..+31, 32 keys) into buffer bf ----
    auto stage_k = [&](int t, int h, int bf) {
        const uint32_t kd = wbase + (uint32_t)((bf * BUFSZ) << 2);
        const float* kt = kgp + t * 32 * DIM + h * 32;
#pragma unroll
        for (int i = 0; i < 8; ++i) {
            int c = i * 32 + lane;               // 0..255
            int k = c >> 3, i2 = c & 7;
            cp16(kd + (uint32_t)((k * KHROW + i2 * 4) << 2),
                 kt + k * DIM + i2 * 4);
        }
        cp_commit();
    };
    // ---- stage V half vh of tile t (keys 16vh..+15, full rows) into buffer bf ----
    auto stage_v = [&](int t, int vh, int bf) {
        const uint32_t vd = wbase + (uint32_t)((bf * BUFSZ) << 2);
        const float* vt = vgp + (t * 32 + vh * 16) * DIM;
#pragma unroll
        for (int i = 0; i < 8; ++i) {
            int c = i * 32 + lane;               // 0..255
            int k = c >> 4, i2 = c & 15;
            cp16(vd + (uint32_t)((k * DIM + i2 * 4) << 2),
                 vt + k * DIM + i2 * 4);
        }
        cp_commit();
    };

    stage_k(0, 0, 0);
    stage_k(0, 1, 1);

    // ---- Q into smem, prescaled by 1/8 ----
    {
        int r = tid >> 4, s = (tid & 15) << 2;
        float4 qv = *(const float4*)(query + ((size_t)b * NQ + r) * DIM + s);
        qv.x *= 0.125f; qv.y *= 0.125f; qv.z *= 0.125f; qv.w *= 0.125f;
        *(float4*)&smem[OFF_Q + r * QROW + s] = qv;
    }
    __syncthreads();

    float* Wb = &smem[OFF_W(warp)];
    float* Pb = Wb + W_P;
    const float* Qb = &smem[OFF_Q + 2 * mq * QROW];

    float cs0 = 0.f, cs1 = 0.f;
    u64 pv[8];
#pragma unroll
    for (int i = 0; i < 8; ++i) pv[i] = 0ull;

    // ---- QK half: accumulate accp[2r+j] for key kq+8r, query 2mq+j ----
    auto qk_half = [&](const float* Kb, int h, u64* accp) {
        const float* kb = Kb + kq * KHROW;
        const float* qb = Qb + h * 32;
#pragma unroll
        for (int i = 0; i < 8; ++i) {
            ulonglong2 k0 = *(const ulonglong2*)(kb + i * 4);
            ulonglong2 k1 = *(const ulonglong2*)(kb + 8 * KHROW + i * 4);
            ulonglong2 k2 = *(const ulonglong2*)(kb + 16 * KHROW + i * 4);
            ulonglong2 k3 = *(const ulonglong2*)(kb + 24 * KHROW + i * 4);
            ulonglong2 q0 = *(const ulonglong2*)(qb + i * 4);
            ulonglong2 q1 = *(const ulonglong2*)(qb + QROW + i * 4);
            fma2(accp[0], k0.x, q0.x); fma2(accp[0], k0.y, q0.y);
            fma2(accp[1], k0.x, q1.x); fma2(accp[1], k0.y, q1.y);
            fma2(accp[2], k1.x, q0.x); fma2(accp[2], k1.y, q0.y);
            fma2(accp[3], k1.x, q1.x); fma2(accp[3], k1.y, q1.y);
            fma2(accp[4], k2.x, q0.x); fma2(accp[4], k2.y, q0.y);
            fma2(accp[5], k2.x, q1.x); fma2(accp[5], k2.y, q1.y);
            fma2(accp[6], k3.x, q0.x); fma2(accp[6], k3.y, q0.y);
            fma2(accp[7], k3.x, q1.x); fma2(accp[7], k3.y, q1.y);
        }
    };

    // ---- PV half: 16 keys from V buffer ----
    auto pv_half = [&](const float* Vb, int vh) {
#pragma unroll
        for (int k = 0; k < 16; ++k) {
            u64 pl = *(const u64*)&Pb[(vh * 16 + k) * PROW + 2 * mq2];
            u64 ps0 = splat2(f2lo(pl));
            u64 ps1 = splat2(f2hi(pl));
            ulonglong2 v0 = *(const ulonglong2*)(Vb + k * DIM + 4 * vq);
            ulonglong2 v1 = *(const ulonglong2*)(Vb + k * DIM + 32 + 4 * vq);
            fma2(pv[0], ps0, v0.x); fma2(pv[1], ps0, v0.y);
            fma2(pv[2], ps0, v1.x); fma2(pv[3], ps0, v1.y);
            fma2(pv[4], ps1, v0.x); fma2(pv[5], ps1, v0.y);
            fma2(pv[6], ps1, v1.x); fma2(pv[7], ps1, v1.y);
        }
    };

#pragma unroll
    for (int t = 0; t < NT; ++t) {
        u64 accp[8];
#pragma unroll
        for (int i = 0; i < 8; ++i) accp[i] = 0ull;

        cp_wait<1>();  __syncwarp();          // K half 0 (buf0) ready
        qk_half(Wb, 0, accp);
        __syncwarp();
        stage_v(t, 0, 0);                      // buf0 -> V keys 0-15

        cp_wait<1>();  __syncwarp();          // K half 1 (buf1) ready
        qk_half(Wb + BUFSZ, 1, accp);
        __syncwarp();
        stage_v(t, 1, 1);                      // buf1 -> V keys 16-31

        // ---- softmax per key-row r (shfl-sum over the 4 mq lanes) ----
#pragma unroll
        for (int r = 0; r < 4; ++r) {
            float a0 = f2lo(accp[2 * r])     + f2hi(accp[2 * r]);
            float a1 = f2lo(accp[2 * r + 1]) + f2hi(accp[2 * r + 1]);
            float e0 = __expf(a0), e1 = __expf(a1);
            float s = e0 + e1;
            s += __shfl_xor_sync(0xffffffffu, s, 1);
            s += __shfl_xor_sync(0xffffffffu, s, 2);
            float inv = __fdividef(1.0f, s);
            float p0 = fmaf(e0, inv, 1e-8f);
            float p1 = fmaf(e1, inv, 1e-8f);
            cs0 += p0; cs1 += p1;
            *(float2*)&Pb[(kq + 8 * r) * PROW + 2 * mq] = make_float2(p0, p1);
        }
        __syncwarp();                          // P visible to all lanes

        cp_wait<1>();  __syncwarp();          // V half 0 (buf0) ready
        pv_half(Wb, 0);
        __syncwarp();
        if (t + 1 < NT) stage_k(t + 1, 0, 0);

        if (t + 1 < NT) { cp_wait<1>(); } else { cp_wait<0>(); }
        __syncwarp();                          // V half 1 (buf1) ready
        pv_half(Wb + BUFSZ, 1);
        __syncwarp();
        if (t + 1 < NT) stage_k(t + 1, 1, 1);
    }

    // ================= per-warp epilogue =================
    {
        // colsum: reduce over the 8 kq groups (lane bits 2..4)
        cs0 += __shfl_xor_sync(0xffffffffu, cs0, 4);
        cs0 += __shfl_xor_sync(0xffffffffu, cs0, 8);
        cs0 += __shfl_xor_sync(0xffffffffu, cs0, 16);
        cs1 += __shfl_xor_sync(0xffffffffu, cs1, 4);
        cs1 += __shfl_xor_sync(0xffffffffu, cs1, 8);
        cs1 += __shfl_xor_sync(0xffffffffu, cs1, 16);

        float* red = Wb;                       // buffer0 region, fully drained
        __syncwarp();
#pragma unroll
        for (int j = 0; j < 2; ++j) {
            int m = 2 * mq2 + j;
            ulonglong2 w0 = make_ulonglong2(pv[4 * j + 0], pv[4 * j + 1]);
            ulonglong2 w1 = make_ulonglong2(pv[4 * j + 2], pv[4 * j + 3]);
            *(ulonglong2*)&red[m * 64 + 4 * vq]      = w0;
            *(ulonglong2*)&red[m * 64 + 32 + 4 * vq] = w1;
        }
        if (lane < 4) {                        // lane == mq with kq == 0
            red[512 + 2 * lane]     = cs0;
            red[512 + 2 * lane + 1] = cs1;
        }
    }
    __syncthreads();

    const int pidx = (b * CPB + chunk) * NQ;
    if (tid < 8) {
        float s = 0.f;
#pragma unroll
        for (int w = 0; w < 4; ++w) s += smem[OFF_W(w) + 512 + tid];
        g_cs[pidx + tid] = s;
    }
    {
        int off = tid * 4;                    // 128 threads x float4 = 512 floats
        float4 s = make_float4(0.f, 0.f, 0.f, 0.f);
#pragma unroll
        for (int w = 0; w < 4; ++w) {
            float4 p = *(const float4*)&smem[OFF_W(w) + off];
            s.x += p.x; s.y += p.y; s.z += p.z; s.w += p.w;
        }
        *(float4*)&g_pv[(size_t)pidx * DIM + off] = s;
    }

    // ---- fused finalize: last chunk CTA of this batch ----
    __syncthreads();
    if (tid == 0) {
        __threadfence();
        unsigned old = atomicAdd(&g_cnt[b], 1u);
        s_last = (old == CPB - 1) ? 1 : 0;
    }
    __syncthreads();
    if (s_last) {
        __threadfence();
        int qm = tid >> 4, v4 = (tid & 15) << 2;
        float c0 = 0.f;
        float4 acc4 = make_float4(0.f, 0.f, 0.f, 0.f);
#pragma unroll
        for (int c = 0; c < CPB; ++c) {
            c0 += g_cs[(b * CPB + c) * NQ + qm];
            float4 p = *(const float4*)&g_pv[((size_t)(b * CPB + c) * NQ + qm) * DIM + v4];
            acc4.x += p.x; acc4.y += p.y; acc4.z += p.z; acc4.w += p.w;
        }
        float inv = 1.0f / c0;
        *(float4*)&out[((size_t)b * NQ + qm) * DIM + v4] =
            make_float4(acc4.x * inv, acc4.y * inv, acc4.z * inv, acc4.w * inv);
        if (tid == 0) g_cnt[b] = 0;   // reset for next graph replay
    }
}

extern "C" void kernel_launch(void* const* d_in, const int* in_sizes, int n_in,
                              void* d_out, int out_size) {
    const float* keys  = (const float*)d_in[0];
    const float* vals  = (const float*)d_in[1];
    const float* query = (const float*)d_in[2];
    float* out = (float*)d_out;

    cudaFuncSetAttribute(attn_fused,
                         cudaFuncAttributeMaxDynamicSharedMemorySize,
                         SMEM_FLOATS * sizeof(float));
    attn_fused<<<BQ * CPB, 128, SMEM_FLOATS * sizeof(float)>>>(keys, vals, query, out);
}

// round 16
// speedup vs baseline: 1.3266x; 1.1201x over previous
#include <cuda_runtime.h>
#include <cstdint>

#define BQ     32
#define NKEYS  4096
#define DIM    64
#define NQ     8
#define CPB    16         // chunks per batch -> grid 512
#define CHUNK  256        // keys per CTA (4 warps x 64)
#define WKEYS  64         // keys per warp: 2 tiles of 32
#define NT     2
#define KHROW  36         // K half-row stride (32 + 4 pad); conflict-free kq reads
#define PROW   10         // P row stride (8 + 2 pad)
#define QROW   68         // Q row stride (64 + 4 pad)
#define BUFSZ  1152       // ring buffer: K half (32x36) or V half (16x64=1024)

typedef unsigned long long u64;

// ---- global scratch ----
__device__ float    g_pv[BQ * CPB * NQ * DIM];
__device__ float    g_cs[BQ * CPB * NQ];
__device__ unsigned g_cnt[BQ];

// ---- cp.async (16B, for K) ----
__device__ __forceinline__ void cp16(uint32_t s, const float* g) {
    asm volatile("cp.async.cg.shared.global [%0], [%1], 16;\n" :: "r"(s), "l"(g));
}
__device__ __forceinline__ void cp_commit() {
    asm volatile("cp.async.commit_group;\n" ::: "memory");
}
template <int N>
__device__ __forceinline__ void cp_wait() {
    asm volatile("cp.async.wait_group %0;\n" :: "n"(N) : "memory");
}

// ---- bulk copy + mbarrier (for V) ----
__device__ __forceinline__ void mbar_init(uint32_t mbar, uint32_t cnt) {
    asm volatile("mbarrier.init.shared.b64 [%0], %1;" :: "r"(mbar), "r"(cnt) : "memory");
}
__device__ __forceinline__ void mbar_expect_tx(uint32_t mbar, uint32_t bytes) {
    asm volatile("mbarrier.arrive.expect_tx.shared.b64 _, [%0], %1;"
                 :: "r"(mbar), "r"(bytes) : "memory");
}
__device__ __forceinline__ void bulk_cp(uint32_t dst, const float* src,
                                        uint32_t bytes, uint32_t mbar) {
    asm volatile("cp.async.bulk.shared::cta.global.mbarrier::complete_tx::bytes "
                 "[%0], [%1], %2, [%3];"
                 :: "r"(dst), "l"(src), "r"(bytes), "r"(mbar) : "memory");
}
__device__ __forceinline__ void mbar_wait(uint32_t mbar, uint32_t parity) {
    asm volatile(
        "{\n\t.reg .pred P1;\n\t"
        "WAIT_LOOP_%=:\n\t"
        "mbarrier.try_wait.parity.acquire.cta.shared::cta.b64 P1, [%0], %1, 0x989680;\n\t"
        "@P1 bra.uni WAIT_DONE_%=;\n\t"
        "bra.uni WAIT_LOOP_%=;\n\t"
        "WAIT_DONE_%=:\n\t}"
        :: "r"(mbar), "r"(parity) : "memory");
}

// ---- packed f32x2 ----
__device__ __forceinline__ void fma2(u64& d, u64 a, u64 b) {
    asm("fma.rn.f32x2 %0, %1, %2, %0;" : "+l"(d) : "l"(a), "l"(b));
}
__device__ __forceinline__ float f2lo(u64 x) { return __uint_as_float((unsigned)x); }
__device__ __forceinline__ float f2hi(u64 x) { return __uint_as_float((unsigned)(x >> 32)); }
__device__ __forceinline__ u64 splat2(float p) {
    u64 r; asm("mov.b64 %0, {%1, %1};" : "=l"(r) : "f"(p)); return r;
}

// ---- smem layout (float offsets) ----
// Q (prescaled): 8 x QROW = 544 at 0
// per-warp: buf0 (1152) | buf1 (1152) | P (320) | mbar0,mbar1 (8 floats = 2x8B + pad)
#define W_P     (2 * BUFSZ)                    // 2304
#define W_MBAR  (W_P + 320)                    // 2624 (even -> 8B aligned)
#define W_SZ    (W_MBAR + 8)                   // 2632
#define OFF_Q   0
#define OFF_W(w) (NQ * QROW + (w) * W_SZ)
#define SMEM_FLOATS (NQ * QROW + 4 * W_SZ)     // 11072 floats = 44,288 B -> 5 CTAs/SM

extern __shared__ float smem[];

__global__ __launch_bounds__(128, 5)
void attn_fused(const float* __restrict__ keys,
                const float* __restrict__ vals,
                const float* __restrict__ query,
                float* __restrict__ out) {
    const int tid  = threadIdx.x;
    const int lane = tid & 31;
    const int warp = tid >> 5;
    const int kq   = lane >> 2;        // QK: key group (keys kq+8r)
    const int mq   = lane & 3;         // QK: query pair (2mq, 2mq+1)
    const int mq2  = lane >> 3;        // PV: query pair
    const int vq   = lane & 7;         // PV: v chunks
    const int b     = blockIdx.x >> 4;
    const int chunk = blockIdx.x & 15;
    const int n0    = chunk * CHUNK;
    __shared__ int s_last;

    const uint32_t sbase = (uint32_t)__cvta_generic_to_shared(smem);
    const uint32_t wbase = sbase + (uint32_t)(OFF_W(warp) << 2);
    const uint32_t mb0 = wbase + (uint32_t)(W_MBAR << 2);
    const uint32_t mb1 = mb0 + 8;

    const float* kgp = keys + ((size_t)b * NKEYS + n0 + warp * WKEYS) * DIM;
    const float* vgp = vals + ((size_t)b * NKEYS + n0 + warp * WKEYS) * DIM;

    // ---- stage K half h of tile t into buffer bf (16B cp.async, padded rows) ----
    auto stage_k = [&](int t, int h, int bf) {
        const uint32_t kd = wbase + (uint32_t)((bf * BUFSZ) << 2);
        const float* kt = kgp + t * 32 * DIM + h * 32;
#pragma unroll
        for (int i = 0; i < 8; ++i) {
            int c = i * 32 + lane;
            int k = c >> 3, i2 = c & 7;
            cp16(kd + (uint32_t)((k * KHROW + i2 * 4) << 2),
                 kt + k * DIM + i2 * 4);
        }
        cp_commit();
    };
    // ---- stage V half vh of tile t into buffer bf: ONE bulk copy (4 KB) ----
    auto stage_v = [&](int t, int vh, int bf, uint32_t mb) {
        if (lane == 0) {
            mbar_expect_tx(mb, 4096);
            bulk_cp(wbase + (uint32_t)((bf * BUFSZ) << 2),
                    vgp + (size_t)(t * 32 + vh * 16) * DIM, 4096, mb);
        }
    };

    stage_k(0, 0, 0);
    stage_k(0, 1, 1);
    if (lane == 0) { mbar_init(mb0, 1); mbar_init(mb1, 1); }

    // ---- Q into smem, prescaled by 1/8 ----
    {
        int r = tid >> 4, s = (tid & 15) << 2;
        float4 qv = *(const float4*)(query + ((size_t)b * NQ + r) * DIM + s);
        qv.x *= 0.125f; qv.y *= 0.125f; qv.z *= 0.125f; qv.w *= 0.125f;
        *(float4*)&smem[OFF_Q + r * QROW + s] = qv;
    }
    __syncthreads();   // covers Q visibility AND per-warp mbarrier init

    float* Wb = &smem[OFF_W(warp)];
    float* Pb = Wb + W_P;
    const float* Qb = &smem[OFF_Q + 2 * mq * QROW];

    float cs0 = 0.f, cs1 = 0.f;
    u64 pv[8];
#pragma unroll
    for (int i = 0; i < 8; ++i) pv[i] = 0ull;

    auto qk_half = [&](const float* Kb, int h, u64* accp) {
        const float* kb = Kb + kq * KHROW;
        const float* qb = Qb + h * 32;
#pragma unroll
        for (int i = 0; i < 8; ++i) {
            ulonglong2 k0 = *(const ulonglong2*)(kb + i * 4);
            ulonglong2 k1 = *(const ulonglong2*)(kb + 8 * KHROW + i * 4);
            ulonglong2 k2 = *(const ulonglong2*)(kb + 16 * KHROW + i * 4);
            ulonglong2 k3 = *(const ulonglong2*)(kb + 24 * KHROW + i * 4);
            ulonglong2 q0 = *(const ulonglong2*)(qb + i * 4);
            ulonglong2 q1 = *(const ulonglong2*)(qb + QROW + i * 4);
            fma2(accp[0], k0.x, q0.x); fma2(accp[0], k0.y, q0.y);
            fma2(accp[1], k0.x, q1.x); fma2(accp[1], k0.y, q1.y);
            fma2(accp[2], k1.x, q0.x); fma2(accp[2], k1.y, q0.y);
            fma2(accp[3], k1.x, q1.x); fma2(accp[3], k1.y, q1.y);
            fma2(accp[4], k2.x, q0.x); fma2(accp[4], k2.y, q0.y);
            fma2(accp[5], k2.x, q1.x); fma2(accp[5], k2.y, q1.y);
            fma2(accp[6], k3.x, q0.x); fma2(accp[6], k3.y, q0.y);
            fma2(accp[7], k3.x, q1.x); fma2(accp[7], k3.y, q1.y);
        }
    };

    auto pv_half = [&](const float* Vb, int vh) {
#pragma unroll
        for (int k = 0; k < 16; ++k) {
            u64 pl = *(const u64*)&Pb[(vh * 16 + k) * PROW + 2 * mq2];
            u64 ps0 = splat2(f2lo(pl));
            u64 ps1 = splat2(f2hi(pl));
            ulonglong2 v0 = *(const ulonglong2*)(Vb + k * DIM + 4 * vq);
            ulonglong2 v1 = *(const ulonglong2*)(Vb + k * DIM + 32 + 4 * vq);
            fma2(pv[0], ps0, v0.x); fma2(pv[1], ps0, v0.y);
            fma2(pv[2], ps0, v1.x); fma2(pv[3], ps0, v1.y);
            fma2(pv[4], ps1, v0.x); fma2(pv[5], ps1, v0.y);
            fma2(pv[6], ps1, v1.x); fma2(pv[7], ps1, v1.y);
        }
    };

    int par = 0;   // mbarrier phase parity for this warp (flips each tile)

#pragma unroll
    for (int t = 0; t < NT; ++t) {
        u64 accp[8];
#pragma unroll
        for (int i = 0; i < 8; ++i) accp[i] = 0ull;

        cp_wait<1>();  __syncwarp();          // K half 0 (buf0) ready
        qk_half(Wb, 0, accp);
        __syncwarp();
        stage_v(t, 0, 0, mb0);                 // buf0 -> V keys 0-15 (bulk)

        cp_wait<0>();  __syncwarp();          // K half 1 (buf1) ready
        qk_half(Wb + BUFSZ, 1, accp);
        __syncwarp();
        stage_v(t, 1, 1, mb1);                 // buf1 -> V keys 16-31 (bulk)

        // ---- softmax per key-row r (shfl-sum over the 4 mq lanes) ----
#pragma unroll
        for (int r = 0; r < 4; ++r) {
            float a0 = f2lo(accp[2 * r])     + f2hi(accp[2 * r]);
            float a1 = f2lo(accp[2 * r + 1]) + f2hi(accp[2 * r + 1]);
            float e0 = __expf(a0), e1 = __expf(a1);
            float s = e0 + e1;
            s += __shfl_xor_sync(0xffffffffu, s, 1);
            s += __shfl_xor_sync(0xffffffffu, s, 2);
            float inv = __fdividef(1.0f, s);
            float p0 = fmaf(e0, inv, 1e-8f);
            float p1 = fmaf(e1, inv, 1e-8f);
            cs0 += p0; cs1 += p1;
            *(float2*)&Pb[(kq + 8 * r) * PROW + 2 * mq] = make_float2(p0, p1);
        }
        __syncwarp();                          // P visible to all lanes

        mbar_wait(mb0, par);  __syncwarp();   // V half 0 (buf0) landed
        pv_half(Wb, 0);
        __syncwarp();
        if (t + 1 < NT) stage_k(t + 1, 0, 0);

        mbar_wait(mb1, par);  __syncwarp();   // V half 1 (buf1) landed
        pv_half(Wb + BUFSZ, 1);
        __syncwarp();
        if (t + 1 < NT) stage_k(t + 1, 1, 1);

        par ^= 1;
    }

    // ================= per-warp epilogue =================
    {
        cs0 += __shfl_xor_sync(0xffffffffu, cs0, 4);
        cs0 += __shfl_xor_sync(0xffffffffu, cs0, 8);
        cs0 += __shfl_xor_sync(0xffffffffu, cs0, 16);
        cs1 += __shfl_xor_sync(0xffffffffu, cs1, 4);
        cs1 += __shfl_xor_sync(0xffffffffu, cs1, 8);
        cs1 += __shfl_xor_sync(0xffffffffu, cs1, 16);

        float* red = Wb;                       // buffer0 region, fully drained
        __syncwarp();
#pragma unroll
        for (int j = 0; j < 2; ++j) {
            int m = 2 * mq2 + j;
            ulonglong2 w0 = make_ulonglong2(pv[4 * j + 0], pv[4 * j + 1]);
            ulonglong2 w1 = make_ulonglong2(pv[4 * j + 2], pv[4 * j + 3]);
            *(ulonglong2*)&red[m * 64 + 4 * vq]      = w0;
            *(ulonglong2*)&red[m * 64 + 32 + 4 * vq] = w1;
        }
        if (lane < 4) {
            red[512 + 2 * lane]     = cs0;
            red[512 + 2 * lane + 1] = cs1;
        }
    }
    __syncthreads();

    const int pidx = (b * CPB + chunk) * NQ;
    if (tid < 8) {
        float s = 0.f;
#pragma unroll
        for (int w = 0; w < 4; ++w) s += smem[OFF_W(w) + 512 + tid];
        g_cs[pidx + tid] = s;
    }
    {
        int off = tid * 4;
        float4 s = make_float4(0.f, 0.f, 0.f, 0.f);
#pragma unroll
        for (int w = 0; w < 4; ++w) {
            float4 p = *(const float4*)&smem[OFF_W(w) + off];
            s.x += p.x; s.y += p.y; s.z += p.z; s.w += p.w;
        }
        *(float4*)&g_pv[(size_t)pidx * DIM + off] = s;
    }

    // ---- fused finalize: last chunk CTA of this batch ----
    __syncthreads();
    if (tid == 0) {
        __threadfence();
        unsigned old = atomicAdd(&g_cnt[b], 1u);
        s_last = (old == CPB - 1) ? 1 : 0;
    }
    __syncthreads();
    if (s_last) {
        __threadfence();
        int qm = tid >> 4, v4 = (tid & 15) << 2;
        float c0 = 0.f;
        float4 acc4 = make_float4(0.f, 0.f, 0.f, 0.f);
#pragma unroll
        for (int c = 0; c < CPB; ++c) {
            c0 += g_cs[(b * CPB + c) * NQ + qm];
            float4 p = *(const float4*)&g_pv[((size_t)(b * CPB + c) * NQ + qm) * DIM + v4];
            acc4.x += p.x; acc4.y += p.y; acc4.z += p.z; acc4.w += p.w;
        }
        float inv = 1.0f / c0;
        *(float4*)&out[((size_t)b * NQ + qm) * DIM + v4] =
            make_float4(acc4.x * inv, acc4.y * inv, acc4.z * inv, acc4.w * inv);
        if (tid == 0) g_cnt[b] = 0;   // reset for next graph replay
    }
}

extern "C" void kernel_launch(void* const* d_in, const int* in_sizes, int n_in,
                              void* d_out, int out_size) {
    const float* keys  = (const float*)d_in[0];
    const float* vals  = (const float*)d_in[1];
    const float* query = (const float*)d_in[2];
    float* out = (float*)d_out;

    cudaFuncSetAttribute(attn_fused,
                         cudaFuncAttributeMaxDynamicSharedMemorySize,
                         SMEM_FLOATS * sizeof(float));
    attn_fused<<<BQ * CPB, 128, SMEM_FLOATS * sizeof(float)>>>(keys, vals, query, out);
}

// round 17
// speedup vs baseline: 1.4877x; 1.1214x over previous
#include <cuda_runtime.h>
#include <cstdint>

#define BQ     32
#define NKEYS  4096
#define DIM    64
#define NQ     8
#define CPB    16         // chunks per batch -> grid 512
#define CHUNK  256        // keys per CTA (4 warps x 64)
#define WKEYS  64         // keys per warp: 2 tiles of 32
#define NT     2
#define KHROW  36         // K half-row stride (32 + 4 pad); conflict-free kq reads
#define PROW   12         // P row stride (8 used + 4 pad) -> 48B rows, 16B-aligned
#define QROW   68         // Q row stride (64 + 4 pad)
#define BUFSZ  1152       // ring buffer: K half (32x36) or V half (16x64=1024)

typedef unsigned long long u64;

// ---- global scratch ----
__device__ float    g_pv[BQ * CPB * NQ * DIM];
__device__ float    g_cs[BQ * CPB * NQ];
__device__ unsigned g_cnt[BQ];

// ---- cp.async (16B, for K) ----
__device__ __forceinline__ void cp16(uint32_t s, const float* g) {
    asm volatile("cp.async.cg.shared.global [%0], [%1], 16;\n" :: "r"(s), "l"(g));
}
__device__ __forceinline__ void cp_commit() {
    asm volatile("cp.async.commit_group;\n" ::: "memory");
}
template <int N>
__device__ __forceinline__ void cp_wait() {
    asm volatile("cp.async.wait_group %0;\n" :: "n"(N) : "memory");
}

// ---- bulk copy + mbarrier (for V) ----
__device__ __forceinline__ void mbar_init(uint32_t mbar, uint32_t cnt) {
    asm volatile("mbarrier.init.shared.b64 [%0], %1;" :: "r"(mbar), "r"(cnt) : "memory");
}
__device__ __forceinline__ void mbar_expect_tx(uint32_t mbar, uint32_t bytes) {
    asm volatile("mbarrier.arrive.expect_tx.shared.b64 _, [%0], %1;"
                 :: "r"(mbar), "r"(bytes) : "memory");
}
__device__ __forceinline__ void bulk_cp(uint32_t dst, const float* src,
                                        uint32_t bytes, uint32_t mbar) {
    asm volatile("cp.async.bulk.shared::cta.global.mbarrier::complete_tx::bytes "
                 "[%0], [%1], %2, [%3];"
                 :: "r"(dst), "l"(src), "r"(bytes), "r"(mbar) : "memory");
}
__device__ __forceinline__ void mbar_wait(uint32_t mbar, uint32_t parity) {
    asm volatile(
        "{\n\t.reg .pred P1;\n\t"
        "WAIT_LOOP_%=:\n\t"
        "mbarrier.try_wait.parity.acquire.cta.shared::cta.b64 P1, [%0], %1, 0x989680;\n\t"
        "@P1 bra.uni WAIT_DONE_%=;\n\t"
        "bra.uni WAIT_LOOP_%=;\n\t"
        "WAIT_DONE_%=:\n\t}"
        :: "r"(mbar), "r"(parity) : "memory");
}

// ---- packed f32x2 ----
__device__ __forceinline__ void fma2(u64& d, u64 a, u64 b) {
    asm("fma.rn.f32x2 %0, %1, %2, %0;" : "+l"(d) : "l"(a), "l"(b));
}
__device__ __forceinline__ float f2lo(u64 x) { return __uint_as_float((unsigned)x); }
__device__ __forceinline__ float f2hi(u64 x) { return __uint_as_float((unsigned)(x >> 32)); }
__device__ __forceinline__ u64 splat2(float p) {
    u64 r; asm("mov.b64 %0, {%1, %1};" : "=l"(r) : "f"(p)); return r;
}

// ---- smem layout (float offsets) ----
// Q (prescaled): 8 x QROW = 544 at 0
// per-warp: buf0 (1152) | buf1 (1152) | P (32x12=384) | mbar0,mbar1 (8 floats)
// epilogue overlays buf0: two parity slices of 520 + cs[8] at 1040.
#define W_P     (2 * BUFSZ)                    // 2304
#define W_MBAR  (W_P + 384)                    // 2688
#define W_SZ    (W_MBAR + 8)                   // 2696
#define OFF_Q   0
#define OFF_W(w) (NQ * QROW + (w) * W_SZ)
#define SMEM_FLOATS (NQ * QROW + 4 * W_SZ)     // 11328 floats = 45,312 B

extern __shared__ float smem[];

__global__ __launch_bounds__(128, 4)
void attn_fused(const float* __restrict__ keys,
                const float* __restrict__ vals,
                const float* __restrict__ query,
                float* __restrict__ out) {
    const int tid  = threadIdx.x;
    const int lane = tid & 31;
    const int warp = tid >> 5;
    const int kq   = lane >> 2;        // QK: key group (keys kq+8r)
    const int mq   = lane & 3;         // QK: query pair (2mq, 2mq+1)
    const int kp   = lane >> 4;        // PV: key parity
    const int vq   = lane & 15;        // PV: v quad (dims 4vq..4vq+3)
    const int b     = blockIdx.x >> 4;
    const int chunk = blockIdx.x & 15;
    const int n0    = chunk * CHUNK;
    __shared__ int s_last;

    const uint32_t sbase = (uint32_t)__cvta_generic_to_shared(smem);
    const uint32_t wbase = sbase + (uint32_t)(OFF_W(warp) << 2);
    const uint32_t mb0 = wbase + (uint32_t)(W_MBAR << 2);
    const uint32_t mb1 = mb0 + 8;

    const float* kgp = keys + ((size_t)b * NKEYS + n0 + warp * WKEYS) * DIM;
    const float* vgp = vals + ((size_t)b * NKEYS + n0 + warp * WKEYS) * DIM;

    // ---- stage K half h of tile t into buffer bf (16B cp.async, padded rows) ----
    auto stage_k = [&](int t, int h, int bf) {
        const uint32_t kd = wbase + (uint32_t)((bf * BUFSZ) << 2);
        const float* kt = kgp + t * 32 * DIM + h * 32;
#pragma unroll
        for (int i = 0; i < 8; ++i) {
            int c = i * 32 + lane;
            int k = c >> 3, i2 = c & 7;
            cp16(kd + (uint32_t)((k * KHROW + i2 * 4) << 2),
                 kt + k * DIM + i2 * 4);
        }
        cp_commit();
    };
    // ---- stage V half vh of tile t into buffer bf: ONE bulk copy (4 KB) ----
    auto stage_v = [&](int t, int vh, int bf, uint32_t mb) {
        if (lane == 0) {
            mbar_expect_tx(mb, 4096);
            bulk_cp(wbase + (uint32_t)((bf * BUFSZ) << 2),
                    vgp + (size_t)(t * 32 + vh * 16) * DIM, 4096, mb);
        }
    };

    stage_k(0, 0, 0);
    stage_k(0, 1, 1);
    if (lane == 0) { mbar_init(mb0, 1); mbar_init(mb1, 1); }

    // ---- Q into smem, prescaled by 1/8 ----
    {
        int r = tid >> 4, s = (tid & 15) << 2;
        float4 qv = *(const float4*)(query + ((size_t)b * NQ + r) * DIM + s);
        qv.x *= 0.125f; qv.y *= 0.125f; qv.z *= 0.125f; qv.w *= 0.125f;
        *(float4*)&smem[OFF_Q + r * QROW + s] = qv;
    }
    __syncthreads();   // covers Q visibility AND per-warp mbarrier init

    float* Wb = &smem[OFF_W(warp)];
    float* Pb = Wb + W_P;
    const float* Qb = &smem[OFF_Q + 2 * mq * QROW];

    float cs0 = 0.f, cs1 = 0.f;
    u64 pv[16];                         // [m][dim-pair]: out[m][4vq + {0,1} / {2,3}]
#pragma unroll
    for (int i = 0; i < 16; ++i) pv[i] = 0ull;

    auto qk_half = [&](const float* Kb, int h, u64* accp) {
        const float* kb = Kb + kq * KHROW;
        const float* qb = Qb + h * 32;
#pragma unroll
        for (int i = 0; i < 8; ++i) {
            ulonglong2 k0 = *(const ulonglong2*)(kb + i * 4);
            ulonglong2 k1 = *(const ulonglong2*)(kb + 8 * KHROW + i * 4);
            ulonglong2 k2 = *(const ulonglong2*)(kb + 16 * KHROW + i * 4);
            ulonglong2 k3 = *(const ulonglong2*)(kb + 24 * KHROW + i * 4);
            ulonglong2 q0 = *(const ulonglong2*)(qb + i * 4);
            ulonglong2 q1 = *(const ulonglong2*)(qb + QROW + i * 4);
            fma2(accp[0], k0.x, q0.x); fma2(accp[0], k0.y, q0.y);
            fma2(accp[1], k0.x, q1.x); fma2(accp[1], k0.y, q1.y);
            fma2(accp[2], k1.x, q0.x); fma2(accp[2], k1.y, q0.y);
            fma2(accp[3], k1.x, q1.x); fma2(accp[3], k1.y, q1.y);
            fma2(accp[4], k2.x, q0.x); fma2(accp[4], k2.y, q0.y);
            fma2(accp[5], k2.x, q1.x); fma2(accp[5], k2.y, q1.y);
            fma2(accp[6], k3.x, q0.x); fma2(accp[6], k3.y, q0.y);
            fma2(accp[7], k3.x, q1.x); fma2(accp[7], k3.y, q1.y);
        }
    };

    // ---- PV half: 16 keys as 8 key-pairs; each V LDS.128 covers 2 whole keys ----
    auto pv_half = [&](const float* Vb, int vh) {
#pragma unroll
        for (int j = 0; j < 8; ++j) {
            int keyp = vh * 16 + 2 * j + kp;                       // this lane's key (P index)
            ulonglong2 pa = *(const ulonglong2*)&Pb[keyp * PROW];      // p0..p3
            ulonglong2 pc = *(const ulonglong2*)&Pb[keyp * PROW + 4];  // p4..p7
            ulonglong2 v  = *(const ulonglong2*)(Vb + (2 * j + kp) * DIM + 4 * vq);
            u64 s0 = splat2(f2lo(pa.x)), s1 = splat2(f2hi(pa.x));
            u64 s2 = splat2(f2lo(pa.y)), s3 = splat2(f2hi(pa.y));
            u64 s4 = splat2(f2lo(pc.x)), s5 = splat2(f2hi(pc.x));
            u64 s6 = splat2(f2lo(pc.y)), s7 = splat2(f2hi(pc.y));
            fma2(pv[0],  s0, v.x); fma2(pv[1],  s0, v.y);
            fma2(pv[2],  s1, v.x); fma2(pv[3],  s1, v.y);
            fma2(pv[4],  s2, v.x); fma2(pv[5],  s2, v.y);
            fma2(pv[6],  s3, v.x); fma2(pv[7],  s3, v.y);
            fma2(pv[8],  s4, v.x); fma2(pv[9],  s4, v.y);
            fma2(pv[10], s5, v.x); fma2(pv[11], s5, v.y);
            fma2(pv[12], s6, v.x); fma2(pv[13], s6, v.y);
            fma2(pv[14], s7, v.x); fma2(pv[15], s7, v.y);
        }
    };

    int par = 0;   // mbarrier phase parity (flips each tile)

#pragma unroll
    for (int t = 0; t < NT; ++t) {
        u64 accp[8];
#pragma unroll
        for (int i = 0; i < 8; ++i) accp[i] = 0ull;

        cp_wait<1>();  __syncwarp();          // K half 0 (buf0) ready
        qk_half(Wb, 0, accp);
        __syncwarp();
        stage_v(t, 0, 0, mb0);                 // buf0 -> V keys 0-15 (bulk)

        cp_wait<0>();  __syncwarp();          // K half 1 (buf1) ready
        qk_half(Wb + BUFSZ, 1, accp);
        __syncwarp();
        stage_v(t, 1, 1, mb1);                 // buf1 -> V keys 16-31 (bulk)

        // ---- softmax per key-row r (shfl-sum over the 4 mq lanes) ----
#pragma unroll
        for (int r = 0; r < 4; ++r) {
            float a0 = f2lo(accp[2 * r])     + f2hi(accp[2 * r]);
            float a1 = f2lo(accp[2 * r + 1]) + f2hi(accp[2 * r + 1]);
            float e0 = __expf(a0), e1 = __expf(a1);
            float s = e0 + e1;
            s += __shfl_xor_sync(0xffffffffu, s, 1);
            s += __shfl_xor_sync(0xffffffffu, s, 2);
            float inv = __fdividef(1.0f, s);
            float p0 = fmaf(e0, inv, 1e-8f);
            float p1 = fmaf(e1, inv, 1e-8f);
            cs0 += p0; cs1 += p1;
            *(float2*)&Pb[(kq + 8 * r) * PROW + 2 * mq] = make_float2(p0, p1);
        }
        __syncwarp();                          // P visible to all lanes

        mbar_wait(mb0, par);  __syncwarp();   // V half 0 (buf0) landed
        pv_half(Wb, 0);
        __syncwarp();
        if (t + 1 < NT) stage_k(t + 1, 0, 0);

        mbar_wait(mb1, par);  __syncwarp();   // V half 1 (buf1) landed
        pv_half(Wb + BUFSZ, 1);
        __syncwarp();
        if (t + 1 < NT) stage_k(t + 1, 1, 1);

        par ^= 1;
    }

    // ================= per-warp epilogue =================
    {
        cs0 += __shfl_xor_sync(0xffffffffu, cs0, 4);
        cs0 += __shfl_xor_sync(0xffffffffu, cs0, 8);
        cs0 += __shfl_xor_sync(0xffffffffu, cs0, 16);
        cs1 += __shfl_xor_sync(0xffffffffu, cs1, 4);
        cs1 += __shfl_xor_sync(0xffffffffu, cs1, 8);
        cs1 += __shfl_xor_sync(0xffffffffu, cs1, 16);

        float* red = Wb;                       // buffer0 region, fully drained
        __syncwarp();
        // two parity slices (stride 520): slice kp holds sum over keys of parity kp
#pragma unroll
        for (int m = 0; m < 8; ++m)
            *(ulonglong2*)&red[kp * 520 + m * 64 + 4 * vq] =
                make_ulonglong2(pv[2 * m], pv[2 * m + 1]);
        if (lane < 4) {
            red[1040 + 2 * lane]     = cs0;
            red[1040 + 2 * lane + 1] = cs1;
        }
    }
    __syncthreads();

    const int pidx = (b * CPB + chunk) * NQ;
    if (tid < 8) {
        float s = 0.f;
#pragma unroll
        for (int w = 0; w < 4; ++w) s += smem[OFF_W(w) + 1040 + tid];
        g_cs[pidx + tid] = s;
    }
    {
        int off = tid * 4;                    // 128 threads x float4 = 512 floats
        float4 s = make_float4(0.f, 0.f, 0.f, 0.f);
#pragma unroll
        for (int w = 0; w < 4; ++w) {
#pragma unroll
            for (int pslice = 0; pslice < 2; ++pslice) {
                float4 p = *(const float4*)&smem[OFF_W(w) + pslice * 520 + off];
                s.x += p.x; s.y += p.y; s.z += p.z; s.w += p.w;
            }
        }
        *(float4*)&g_pv[(size_t)pidx * DIM + off] = s;
    }

    // ---- fused finalize: last chunk CTA of this batch ----
    __syncthreads();
    if (tid == 0) {
        __threadfence();
        unsigned old = atomicAdd(&g_cnt[b], 1u);
        s_last = (old == CPB - 1) ? 1 : 0;
    }
    __syncthreads();
    if (s_last) {
        __threadfence();
        int qm = tid >> 4, v4 = (tid & 15) << 2;
        float c0 = 0.f;
        float4 acc4 = make_float4(0.f, 0.f, 0.f, 0.f);
#pragma unroll
        for (int c = 0; c < CPB; ++c) {
            c0 += g_cs[(b * CPB + c) * NQ + qm];
            float4 p = *(const float4*)&g_pv[((size_t)(b * CPB + c) * NQ + qm) * DIM + v4];
            acc4.x += p.x; acc4.y += p.y; acc4.z += p.z; acc4.w += p.w;
        }
        float inv = 1.0f / c0;
        *(float4*)&out[((size_t)b * NQ + qm) * DIM + v4] =
            make_float4(acc4.x * inv, acc4.y * inv, acc4.z * inv, acc4.w * inv);
        if (tid == 0) g_cnt[b] = 0;   // reset for next graph replay
    }
}

extern "C" void kernel_launch(void* const* d_in, const int* in_sizes, int n_in,
                              void* d_out, int out_size) {
    const float* keys  = (const float*)d_in[0];
    const float* vals  = (const float*)d_in[1];
    const float* query = (const float*)d_in[2];
    float* out = (float*)d_out;

    cudaFuncSetAttribute(attn_fused,
                         cudaFuncAttributeMaxDynamicSharedMemorySize,
                         SMEM_FLOATS * sizeof(float));
    attn_fused<<<BQ * CPB, 128, SMEM_FLOATS * sizeof(float)>>>(keys, vals, query, out);
}